// round 11
// baseline (speedup 1.0000x reference)
#include <cuda_runtime.h>
#include <cstdint>

// Problem constants (fixed by setup_inputs: index = 256)
#define B      64
#define S      512
#define D      768
#define H      12
#define TOPK   254          // index - 2
#define NKEEP  255          // index - 1 (top + CLS)
#define NOTHER 257          // S - index + 1
#define D4     (D / 4)      // 192 float4 per row
#define S4     (S / 4)      // 128 float4 per atten row

// -------- scratch (no allocation allowed -> __device__ globals) --------
__device__ __align__(16) float g_part[B * H * S]; // per-(b,h) column sums minus diag
__device__ int   g_rowsrc[B * NKEEP];   // source token index per kept output row
__device__ int   g_osrc[B * NOTHER];    // source token index for "other" set
__device__ float g_ow[B * NOTHER];      // softmax weight / NOTHER
__device__ int   g_cnt[B];              // head-completion counter   (self-resetting)
__device__ int   g_done[B];             // select-done flag          (self-resetting)
__device__ int   g_cnt2[B];             // phase3-completion counter (self-resetting)

// ============================================================
// Single fused kernel. grid = B*H = 768 blocks, 512 threads.
//   phase 1: column sums minus diagonal for plane (b,h) (float4 streaming)
//   phase 2: 12th-arriving block per batch runs selection, publishes g_done[b],
//            then computes the weighted-mean output row (row 255).
//            The other 11 blocks wait on g_done[b] and copy the 255 kept rows
//            (rank r copies rows [r*255/11, (r+1)*255/11)).
// Gather traffic overlaps later batches' colsum streaming -> one launch,
// aggregate-BW-bound.
// ============================================================
__global__ __launch_bounds__(512) void fused_kernel(const float* __restrict__ atten,
                                                    const float4* __restrict__ x4,
                                                    float4* __restrict__ out4) {
    __shared__ float4 s4[4][128];
    __shared__ float  sd[512];
    __shared__ int    s_old;
    __shared__ float  v[512];
    __shared__ int    scan[512];
    __shared__ float  red[512];
    __shared__ float  sw[NOTHER];
    __shared__ int    ss[NOTHER];
    __shared__ float4 sred[2][D4];

    const int bh = blockIdx.x;
    const int b  = bh / H;
    const int t  = threadIdx.x;
    const float* A = atten + (size_t)bh * S * S;
    const float4* xb = x4   + (size_t)b * S   * D4;
    float4*       ob = out4 + (size_t)b * 256 * D4;

    // ---------------- phase 1: plane column-sum ----------------
    {
        const int q   = t & 127;
        const int seg = t >> 7;
        const float4* Ar = (const float4*)A + (size_t)(seg * 128) * S4 + q;

        float4 c0 = make_float4(0.f, 0.f, 0.f, 0.f);
        float4 c1 = make_float4(0.f, 0.f, 0.f, 0.f);
        float4 c2 = make_float4(0.f, 0.f, 0.f, 0.f);
        float4 c3 = make_float4(0.f, 0.f, 0.f, 0.f);
        #pragma unroll 4
        for (int i = 0; i < 128; i += 4) {
            float4 x0 = Ar[(i + 0) * S4];
            float4 x1 = Ar[(i + 1) * S4];
            float4 x2 = Ar[(i + 2) * S4];
            float4 x3 = Ar[(i + 3) * S4];
            c0.x += x0.x; c0.y += x0.y; c0.z += x0.z; c0.w += x0.w;
            c1.x += x1.x; c1.y += x1.y; c1.z += x1.z; c1.w += x1.w;
            c2.x += x2.x; c2.y += x2.y; c2.z += x2.z; c2.w += x2.w;
            c3.x += x3.x; c3.y += x3.y; c3.z += x3.z; c3.w += x3.w;
        }
        float4 cc;
        cc.x = (c0.x + c1.x) + (c2.x + c3.x);
        cc.y = (c0.y + c1.y) + (c2.y + c3.y);
        cc.z = (c0.z + c1.z) + (c2.z + c3.z);
        cc.w = (c0.w + c1.w) + (c2.w + c3.w);
        s4[seg][q] = cc;
        sd[t] = A[(size_t)t * S + t];           // diagonal element j = t
        __syncthreads();

        if (t < 128) {
            float4 a = s4[0][t], bb = s4[1][t], c = s4[2][t], d = s4[3][t];
            float4 tot;
            tot.x = (a.x + bb.x) + (c.x + d.x) - sd[4 * t + 0];
            tot.y = (a.y + bb.y) + (c.y + d.y) - sd[4 * t + 1];
            tot.z = (a.z + bb.z) + (c.z + d.z) - sd[4 * t + 2];
            tot.w = (a.w + bb.w) + (c.w + d.w) - sd[4 * t + 3];
            ((float4*)g_part)[(size_t)bh * 128 + t] = tot;
        }
    }

    // ---------------- completion handshake ----------------
    __threadfence();
    if (t == 0) s_old = atomicAdd(&g_cnt[b], 1);
    __syncthreads();
    const int rank = s_old;                 // 0..11, arrival order within batch

    if (rank == H - 1) {
        // ============ SELECTOR: selection for batch b ============
        __threadfence();                    // acquire: all heads' g_part
        float val = -3.0e38f;
        if (t < S - 1) {
            float s = 0.f;
            #pragma unroll
            for (int h = 0; h < H; h++)
                s += g_part[(b * H + h) * S + (t + 1)];
            val = s * (1.0f / (float)H);
        }
        v[t] = val;
        __syncthreads();

        int r = 0;
        if (t < S - 1) {
            const float mv = val;
            for (int k = 0; k < S - 1; k++) {
                float vk = v[k];
                r += (vk > mv) || (vk == mv && k < t);
            }
        }
        const int flag = (t < S - 1 && r < TOPK) ? 1 : 0;

        scan[t] = flag;
        __syncthreads();
        for (int off = 1; off < 512; off <<= 1) {
            int xx = scan[t];
            int yy = (t >= off) ? scan[t - off] : 0;
            __syncthreads();
            scan[t] = xx + yy;
            __syncthreads();
        }
        const int excl = scan[t] - flag;

        red[t] = (t < S - 1 && !flag) ? val : -3.0e38f;
        __syncthreads();
        for (int off = 256; off > 0; off >>= 1) {
            if (t < off) red[t] = fmaxf(red[t], red[t + off]);
            __syncthreads();
        }
        const float m = red[0];
        __syncthreads();

        const float e = (t < S - 1 && !flag) ? expf(val - m) : 0.f;
        red[t] = e;
        __syncthreads();
        for (int off = 256; off > 0; off >>= 1) {
            if (t < off) red[t] += red[t + off];
            __syncthreads();
        }
        const float Z = red[0];

        float wq = 0.f; int sq = 0;         // this thread's "other" entry (if any)
        if (t < S - 1) {
            if (flag) {
                g_rowsrc[b * NKEEP + 1 + excl] = t + 1;   // slots 1..254, ascending
            } else {
                int p = t - excl;
                sq = t + 1;
                wq = e / (Z * (float)NOTHER);
                g_osrc[b * NOTHER + p] = sq;
                g_ow[b * NOTHER + p]   = wq;
                sw[p] = wq; ss[p] = sq;     // stage locally for weighted row
            }
        }
        if (t == S - 1) g_rowsrc[b * NKEEP] = 0;          // CLS token
        __syncthreads();
        if (t == 0) {
            __threadfence();                              // release select results
            atomicExch(&g_done[b], 1);
        }

        // ---- weighted-mean output row (row 255): 2 groups x 192 cols ----
        if (t < 2 * D4) {
            const int g = t / D4;
            const int c = t - g * D4;
            float4 acc = make_float4(0.f, 0.f, 0.f, 0.f);
            #pragma unroll 4
            for (int q = g; q < NOTHER; q += 2) {
                const float  w  = sw[q];
                const float4 xv = xb[ss[q] * D4 + c];
                acc.x += w * xv.x;
                acc.y += w * xv.y;
                acc.z += w * xv.z;
                acc.w += w * xv.w;
            }
            sred[g][c] = acc;
        }
        __syncthreads();
        if (t < D4) {
            float4 a0 = sred[0][t], a1 = sred[1][t];
            float4 tot;
            tot.x = a0.x + a1.x; tot.y = a0.y + a1.y;
            tot.z = a0.z + a1.z; tot.w = a0.w + a1.w;
            ob[255 * D4 + t] = tot;
        }
    } else {
        // ============ COPIER: wait for select, copy kept-row slice ============
        if (t == 0) {
            while (atomicAdd(&g_done[b], 0) == 0) __nanosleep(200);
        }
        __syncthreads();
        __threadfence();                                  // acquire g_rowsrc

        const int r0 = (rank * NKEEP) / (H - 1);          // rank in 0..10
        const int r1 = ((rank + 1) * NKEEP) / (H - 1);
        const int nrows = r1 - r0;
        const int n = nrows * D4;
        for (int i = t; i < n; i += 512) {
            const int row = i / D4;
            const int col = i - row * D4;
            const int src = __ldg(&g_rowsrc[b * NKEEP + r0 + row]);
            ob[(r0 + row) * D4 + col] = xb[src * D4 + col];
        }
    }

    // ---------------- replay-safe reset ----------------
    __syncthreads();
    if (t == 0) {
        int old2 = atomicAdd(&g_cnt2[b], 1);
        if (old2 == H - 1) {                              // last block of batch b
            g_cnt[b]  = 0;
            g_done[b] = 0;
            g_cnt2[b] = 0;
        }
    }
}

extern "C" void kernel_launch(void* const* d_in, const int* in_sizes, int n_in,
                              void* d_out, int out_size) {
    const float* x     = (const float*)d_in[0];   // (64, 512, 768) f32
    const float* atten = (const float*)d_in[1];   // (768, 512, 512) f32
    // d_in[2] = index (int32, == 256) -- baked into compile-time constants

    fused_kernel<<<B * H, 512>>>(atten, (const float4*)x, (float4*)d_out);
}

// round 13
// speedup vs baseline: 1.2912x; 1.2912x over previous
#include <cuda_runtime.h>
#include <cstdint>

// Problem constants (fixed by setup_inputs: index = 256)
#define B      64
#define S      512
#define D      768
#define H      12
#define TOPK   254          // index - 2
#define NKEEP  255          // index - 1 (top + CLS)
#define NOTHER 257          // S - index + 1
#define D4     (D / 4)      // 192 float4 per row
#define NSPLIT 4            // row-quarters per (b,h) plane
#define QROWS  (S / NSPLIT) // 128 rows per quarter

#define NCOPY_ELEM (B * NKEEP * D4)      // 3,133,440 float4
#define GATHER_THREADS 768
#define NCOPY_BLOCKS (NCOPY_ELEM / GATHER_THREADS)   // 4080 exactly

// -------- scratch (no allocation allowed -> __device__ globals) --------
// fully overwritten every replay; no counters, no resets needed
__device__ float g_part4[B * H * NSPLIT * S]; // per-(b,h,quarter) column sums (diag-adjusted)
__device__ int   g_rowsrc[B * NKEEP];   // source token index per kept output row
__device__ int   g_osrc[B * NOTHER];    // source token index for "other" set
__device__ float g_ow[B * NOTHER];      // softmax weight / NOTHER

// ============================================================
// K1: quarter-plane column sums. grid = B*H*NSPLIT = 3072 blocks, 512 threads.
// Block handles rows [qs*128, qs*128+128) of plane bh; thread j owns column j.
// Lean: ~30 regs, no smem -> 4 blocks/SM, smooth wave structure
// (3072 = 5 full waves of 592 + small 112-block tail of quarter-length work).
// The quarter containing row j subtracts the diagonal element A[j][j].
// ============================================================
__global__ __launch_bounds__(512) void colsum_kernel(const float* __restrict__ atten) {
    const int blk = blockIdx.x;
    const int bh  = blk >> 2;           // plane
    const int qs  = blk & 3;            // quarter
    const int j   = threadIdx.x;
    const float* A = atten + (size_t)bh * S * S + (size_t)qs * QROWS * S;

    float a0 = 0.f, a1 = 0.f, a2 = 0.f, a3 = 0.f;
    float a4 = 0.f, a5 = 0.f, a6 = 0.f, a7 = 0.f;
    for (int i = 0; i < QROWS; i += 8) {
        a0 += A[(i + 0) * S + j];
        a1 += A[(i + 1) * S + j];
        a2 += A[(i + 2) * S + j];
        a3 += A[(i + 3) * S + j];
        a4 += A[(i + 4) * S + j];
        a5 += A[(i + 5) * S + j];
        a6 += A[(i + 6) * S + j];
        a7 += A[(i + 7) * S + j];
    }
    float s = ((a0 + a1) + (a2 + a3)) + ((a4 + a5) + (a6 + a7));
    if ((j >> 7) == qs)                  // this quarter owns row j -> subtract diag
        s -= A[(j - qs * QROWS) * S + j];
    g_part4[(size_t)blk * S + j] = s;
}

// ============================================================
// K2: per-batch selection. grid = B blocks, 512 threads.
// Reduce 12 heads x 4 quarters -> ab[t]; exact rank with jax top_k tie-break;
// prefix-scan compaction; softmax weights over the 257-element "other" set.
// ============================================================
__global__ __launch_bounds__(512) void select_kernel() {
    __shared__ float v[512];
    __shared__ int   scan[512];
    __shared__ float red[512];

    const int b = blockIdx.x;
    const int t = threadIdx.x;          // token index = t + 1

    float val = -3.0e38f;
    if (t < S - 1) {
        float s = 0.f;
        const float* p = g_part4 + (size_t)(b * H * NSPLIT) * S + (t + 1);
        #pragma unroll
        for (int h = 0; h < H * NSPLIT; h++)
            s += p[h * S];
        val = s * (1.0f / (float)H);
    }
    v[t] = val;
    __syncthreads();

    // exact rank (lower index wins ties, matching jax top_k)
    int r = 0;
    if (t < S - 1) {
        const float mv = val;
        for (int k = 0; k < S - 1; k++) {
            float vk = v[k];
            r += (vk > mv) || (vk == mv && k < t);
        }
    }
    const int flag = (t < S - 1 && r < TOPK) ? 1 : 0;

    // inclusive Hillis-Steele scan of flags
    scan[t] = flag;
    __syncthreads();
    for (int off = 1; off < 512; off <<= 1) {
        int x = scan[t];
        int y = (t >= off) ? scan[t - off] : 0;
        __syncthreads();
        scan[t] = x + y;
        __syncthreads();
    }
    const int excl = scan[t] - flag;

    // softmax over "other": max then sum
    red[t] = (t < S - 1 && !flag) ? val : -3.0e38f;
    __syncthreads();
    for (int off = 256; off > 0; off >>= 1) {
        if (t < off) red[t] = fmaxf(red[t], red[t + off]);
        __syncthreads();
    }
    const float m = red[0];
    __syncthreads();

    const float e = (t < S - 1 && !flag) ? expf(val - m) : 0.f;
    red[t] = e;
    __syncthreads();
    for (int off = 256; off > 0; off >>= 1) {
        if (t < off) red[t] += red[t + off];
        __syncthreads();
    }
    const float Z = red[0];

    if (t < S - 1) {
        if (flag) {
            g_rowsrc[b * NKEEP + 1 + excl] = t + 1;       // slots 1..254, ascending
        } else {
            int p = t - excl;
            g_osrc[b * NOTHER + p] = t + 1;
            g_ow[b * NOTHER + p]   = e / (Z * (float)NOTHER);
        }
    }
    if (t == S - 1) g_rowsrc[b * NKEEP] = 0;              // CLS token
}

// ============================================================
// K3: output assembly, flat grid, 768 threads. (round-10 proven version)
//   blocks 0..63       : weighted-mean row (out row 255) for batch b
//   blocks 64..64+4079 : pure memcpy-shaped copy, exactly 1 float4/thread
// ============================================================
__global__ __launch_bounds__(GATHER_THREADS) void gather_kernel(const float4* __restrict__ x4,
                                                                float4* __restrict__ out4) {
    const int t = threadIdx.x;

    if (blockIdx.x < B) {
        const int b = blockIdx.x;
        const float4* xb = x4 + (size_t)b * S * D4;

        __shared__ float  sw[NOTHER];
        __shared__ int    ss[NOTHER];
        __shared__ float4 sred[4][D4];

        if (t < NOTHER) {
            sw[t] = g_ow[b * NOTHER + t];
            ss[t] = g_osrc[b * NOTHER + t];
        }
        __syncthreads();

        const int g = t / D4;        // row group 0..3
        const int c = t % D4;        // column (float4)
        float4 acc = make_float4(0.f, 0.f, 0.f, 0.f);
        #pragma unroll 4
        for (int q = g; q < NOTHER; q += 4) {
            const float  w  = sw[q];
            const float4 xv = xb[ss[q] * D4 + c];
            acc.x += w * xv.x;
            acc.y += w * xv.y;
            acc.z += w * xv.z;
            acc.w += w * xv.w;
        }
        sred[g][c] = acc;
        __syncthreads();

        if (t < D4) {
            float4 a0 = sred[0][t], a1 = sred[1][t], a2 = sred[2][t], a3 = sred[3][t];
            float4 tot;
            tot.x = (a0.x + a1.x) + (a2.x + a3.x);
            tot.y = (a0.y + a1.y) + (a2.y + a3.y);
            tot.z = (a0.z + a1.z) + (a2.z + a3.z);
            tot.w = (a0.w + a1.w) + (a2.w + a3.w);
            out4[((size_t)b * 256 + 255) * D4 + t] = tot;
        }
    } else {
        const int e   = (blockIdx.x - B) * GATHER_THREADS + t;   // < NCOPY_ELEM
        const int b   = e / (NKEEP * D4);
        const int rem = e - b * (NKEEP * D4);
        const int row = rem / D4;
        const int col = rem - row * D4;
        const int src = __ldg(&g_rowsrc[b * NKEEP + row]);
        out4[((size_t)b * 256 + row) * D4 + col] = x4[((size_t)b * S + src) * D4 + col];
    }
}

extern "C" void kernel_launch(void* const* d_in, const int* in_sizes, int n_in,
                              void* d_out, int out_size) {
    const float* x     = (const float*)d_in[0];   // (64, 512, 768) f32
    const float* atten = (const float*)d_in[1];   // (768, 512, 512) f32
    // d_in[2] = index (int32, == 256) -- baked into compile-time constants

    colsum_kernel<<<B * H * NSPLIT, 512>>>(atten);
    select_kernel<<<B, 512>>>();
    gather_kernel<<<B + NCOPY_BLOCKS, GATHER_THREADS>>>((const float4*)x, (float4*)d_out);
}

// round 14
// speedup vs baseline: 1.3080x; 1.0130x over previous
#include <cuda_runtime.h>
#include <cstdint>

// Problem constants (fixed by setup_inputs: index = 256)
#define B      64
#define S      512
#define D      768
#define H      12
#define TOPK   254          // index - 2
#define NKEEP  255          // index - 1 (top + CLS)
#define NOTHER 257          // S - index + 1
#define D4     (D / 4)      // 192 float4 per row
#define NSPLIT 4            // row-quarters per (b,h) plane
#define QROWS  (S / NSPLIT) // 128 rows per quarter

#define NCOPY_ELEM (B * NKEEP * D4)      // 3,133,440 float4
#define GATHER_THREADS 768
#define COPY_PER_THREAD 4
#define COPY_BLK  (GATHER_THREADS * COPY_PER_THREAD)   // 3072
#define NCOPY_BLOCKS (NCOPY_ELEM / COPY_BLK)           // 1020 exactly

// -------- scratch (no allocation allowed -> __device__ globals) --------
// fully overwritten every replay; no counters, no resets needed
__device__ float g_part4[B * H * NSPLIT * S]; // per-(b,h,quarter) column sums (diag-adjusted)
__device__ int   g_rowsrc[B * NKEEP];   // source token index per kept output row
__device__ int   g_osrc[B * NOTHER];    // source token index for "other" set
__device__ float g_ow[B * NOTHER];      // softmax weight / NOTHER

// ============================================================
// K1: quarter-plane column sums. grid = B*H*NSPLIT = 3072 blocks, 512 threads.
// Thread j owns column j; 8 independent accumulators; __ldcs (read-once stream).
// ============================================================
__global__ __launch_bounds__(512) void colsum_kernel(const float* __restrict__ atten) {
    const int blk = blockIdx.x;
    const int bh  = blk >> 2;           // plane
    const int qs  = blk & 3;            // quarter
    const int j   = threadIdx.x;
    const float* A = atten + (size_t)bh * S * S + (size_t)qs * QROWS * S;

    float a0 = 0.f, a1 = 0.f, a2 = 0.f, a3 = 0.f;
    float a4 = 0.f, a5 = 0.f, a6 = 0.f, a7 = 0.f;
    for (int i = 0; i < QROWS; i += 8) {
        a0 += __ldcs(&A[(i + 0) * S + j]);
        a1 += __ldcs(&A[(i + 1) * S + j]);
        a2 += __ldcs(&A[(i + 2) * S + j]);
        a3 += __ldcs(&A[(i + 3) * S + j]);
        a4 += __ldcs(&A[(i + 4) * S + j]);
        a5 += __ldcs(&A[(i + 5) * S + j]);
        a6 += __ldcs(&A[(i + 6) * S + j]);
        a7 += __ldcs(&A[(i + 7) * S + j]);
    }
    float s = ((a0 + a1) + (a2 + a3)) + ((a4 + a5) + (a6 + a7));
    if ((j >> 7) == qs)                  // this quarter owns row j -> subtract diag
        s -= A[(j - qs * QROWS) * S + j];
    g_part4[(size_t)blk * S + j] = s;
}

// ============================================================
// K2: per-batch selection. grid = B blocks, 512 threads. (proven verbatim)
// ============================================================
__global__ __launch_bounds__(512) void select_kernel() {
    __shared__ float v[512];
    __shared__ int   scan[512];
    __shared__ float red[512];

    const int b = blockIdx.x;
    const int t = threadIdx.x;          // token index = t + 1

    float val = -3.0e38f;
    if (t < S - 1) {
        float s = 0.f;
        const float* p = g_part4 + (size_t)(b * H * NSPLIT) * S + (t + 1);
        #pragma unroll
        for (int h = 0; h < H * NSPLIT; h++)
            s += p[h * S];
        val = s * (1.0f / (float)H);
    }
    v[t] = val;
    __syncthreads();

    // exact rank (lower index wins ties, matching jax top_k)
    int r = 0;
    if (t < S - 1) {
        const float mv = val;
        for (int k = 0; k < S - 1; k++) {
            float vk = v[k];
            r += (vk > mv) || (vk == mv && k < t);
        }
    }
    const int flag = (t < S - 1 && r < TOPK) ? 1 : 0;

    // inclusive Hillis-Steele scan of flags
    scan[t] = flag;
    __syncthreads();
    for (int off = 1; off < 512; off <<= 1) {
        int x = scan[t];
        int y = (t >= off) ? scan[t - off] : 0;
        __syncthreads();
        scan[t] = x + y;
        __syncthreads();
    }
    const int excl = scan[t] - flag;

    // softmax over "other": max then sum
    red[t] = (t < S - 1 && !flag) ? val : -3.0e38f;
    __syncthreads();
    for (int off = 256; off > 0; off >>= 1) {
        if (t < off) red[t] = fmaxf(red[t], red[t + off]);
        __syncthreads();
    }
    const float m = red[0];
    __syncthreads();

    const float e = (t < S - 1 && !flag) ? expf(val - m) : 0.f;
    red[t] = e;
    __syncthreads();
    for (int off = 256; off > 0; off >>= 1) {
        if (t < off) red[t] += red[t + off];
        __syncthreads();
    }
    const float Z = red[0];

    if (t < S - 1) {
        if (flag) {
            g_rowsrc[b * NKEEP + 1 + excl] = t + 1;       // slots 1..254, ascending
        } else {
            int p = t - excl;
            g_osrc[b * NOTHER + p] = t + 1;
            g_ow[b * NOTHER + p]   = e / (Z * (float)NOTHER);
        }
    }
    if (t == S - 1) g_rowsrc[b * NKEEP] = 0;              // CLS token
}

// ============================================================
// K3: output assembly, flat grid, 768 threads.
//   blocks 0..63       : weighted-mean row (out row 255) for batch b
//   blocks 64..64+1019 : copy kept rows, 4 float4 per thread (independent
//                        chains -> MLP ~8), __ldcs on read-once x data.
// ============================================================
__global__ __launch_bounds__(GATHER_THREADS) void gather_kernel(const float4* __restrict__ x4,
                                                                float4* __restrict__ out4) {
    const int t = threadIdx.x;

    if (blockIdx.x < B) {
        const int b = blockIdx.x;
        const float4* xb = x4 + (size_t)b * S * D4;

        __shared__ float  sw[NOTHER];
        __shared__ int    ss[NOTHER];
        __shared__ float4 sred[4][D4];

        if (t < NOTHER) {
            sw[t] = g_ow[b * NOTHER + t];
            ss[t] = g_osrc[b * NOTHER + t];
        }
        __syncthreads();

        const int g = t / D4;        // row group 0..3
        const int c = t % D4;        // column (float4)
        float4 acc = make_float4(0.f, 0.f, 0.f, 0.f);
        #pragma unroll 4
        for (int q = g; q < NOTHER; q += 4) {
            const float  w  = sw[q];
            const float4 xv = xb[ss[q] * D4 + c];
            acc.x += w * xv.x;
            acc.y += w * xv.y;
            acc.z += w * xv.z;
            acc.w += w * xv.w;
        }
        sred[g][c] = acc;
        __syncthreads();

        if (t < D4) {
            float4 a0 = sred[0][t], a1 = sred[1][t], a2 = sred[2][t], a3 = sred[3][t];
            float4 tot;
            tot.x = (a0.x + a1.x) + (a2.x + a3.x);
            tot.y = (a0.y + a1.y) + (a2.y + a3.y);
            tot.z = (a0.z + a1.z) + (a2.z + a3.z);
            tot.w = (a0.w + a1.w) + (a2.w + a3.w);
            out4[((size_t)b * 256 + 255) * D4 + t] = tot;
        }
    } else {
        // ---- copy kept rows: 4 independent float4 chains per thread ----
        const int base = (blockIdx.x - B) * COPY_BLK + t;
        #pragma unroll
        for (int k = 0; k < COPY_PER_THREAD; k++) {
            const int e   = base + k * GATHER_THREADS;    // < NCOPY_ELEM
            const int b   = e / (NKEEP * D4);
            const int rem = e - b * (NKEEP * D4);
            const int row = rem / D4;
            const int col = rem - row * D4;
            const int src = __ldg(&g_rowsrc[b * NKEEP + row]);
            const float4 val = __ldcs(&x4[((size_t)b * S + src) * D4 + col]);
            out4[((size_t)b * 256 + row) * D4 + col] = val;
        }
    }
}

extern "C" void kernel_launch(void* const* d_in, const int* in_sizes, int n_in,
                              void* d_out, int out_size) {
    const float* x     = (const float*)d_in[0];   // (64, 512, 768) f32
    const float* atten = (const float*)d_in[1];   // (768, 512, 512) f32
    // d_in[2] = index (int32, == 256) -- baked into compile-time constants

    colsum_kernel<<<B * H * NSPLIT, 512>>>(atten);
    select_kernel<<<B, 512>>>();
    gather_kernel<<<B + NCOPY_BLOCKS, GATHER_THREADS>>>((const float4*)x, (float4*)d_out);
}